// round 8
// baseline (speedup 1.0000x reference)
#include <cuda_runtime.h>
#include <math.h>

// ---------------------------------------------------------------------------
// GCN(2)->node0->LSTM->FC. Only the 2-hop in-neighborhood of node 0 matters:
// S1 = in-neighbors of 0 (~32), S2 = in-neighbors of S1 (~1100).
// Seven PDL-chained kernels (launch prep overlaps predecessor tails):
//   init  : incremental reset of prev-run entries (1 block), seed node 0
//   scan1 : dst==0            -> e0 list, S1 set, bm1
//   scan2 : dst in bm1 (SMEM) -> e1 list, S2 set, bm2
//   hlin  : x[:,u]@W1 for u in S2   (triggers PDL early -> overlaps scan3)
//   scan3 : dst in bm2 (SMEM) -> deg       (runs CONCURRENTLY with hlin)
//   agg   : layer-1 aggregation into acc1 (waits hlin flag + scan3 via PDL)
//   tail  : one block: h2 = relu(acc1+b1)@W2 ; node-0 layer-2 agg ; LSTM ; FC
// ---------------------------------------------------------------------------

#define NN_MAX   100000
#define IND      128
#define H        64
#define S1CAP    512
#define E0CAP    2048
#define ECAP     32768
#define BMW      ((NN_MAX + 31) / 32)   // 3125 words = 12.5 KB
#define SCAN_B   296
#define SCAN_T   512
#define HLIN_B   148

static __device__ int      g_deg[NN_MAX];
static __device__ int      g_flag1[NN_MAX];   // pos+1 in S1 (0 = not member)
static __device__ int      g_flag2[NN_MAX];   // pos+1 in S2
static __device__ unsigned g_bm1[BMW];
static __device__ unsigned g_bm2[BMW];
static __device__ int      g_s1[S1CAP];
static __device__ int      g_e0[E0CAP];       // src of edges with dst==0
static __device__ int      g_s2[ECAP];
static __device__ int2     g_e1[ECAP];        // edges with dst in S1
static __device__ int      g_cnt1, g_cnt2, g_cntE0, g_cntE1;
static __device__ float    g_hlin[ECAP][H];
static __device__ float    g_acc1[S1CAP][H];
static __device__ float    g_h2[S1CAP][H];
static __device__ unsigned g_hlin_done;       // hlin completion counter

// ---------------------------------------------------------------------------
// Incremental init: reset exactly the entries the previous run touched,
// then seed node 0. First call sees counters==0 (static zero-init) -> no-op
// loops, seed only. Always leaves the identical canonical state.
__global__ void k_init(void) {
    cudaGridDependencySynchronize();
    int tid = threadIdx.x;
    int m1 = g_cnt1; if (m1 > S1CAP) m1 = S1CAP;
    int m2 = g_cnt2; if (m2 > ECAP)  m2 = ECAP;
    for (int j = 1 + tid; j < m1; j += 512) {
        int u = g_s1[j];
        g_flag1[u] = 0;
        atomicAnd(&g_bm1[u >> 5], ~(1u << (u & 31)));
    }
    for (int j = 1 + tid; j < m2; j += 512) {
        int u = g_s2[j];
        g_flag2[u] = 0;
        g_deg[u]   = 0;
        atomicAnd(&g_bm2[u >> 5], ~(1u << (u & 31)));
    }
    for (int k = tid; k < m1 * H; k += 512) ((float*)g_acc1)[k] = 0.0f;
    __syncthreads();
    if (tid == 0) {
        g_cnt1 = 1; g_cnt2 = 1; g_cntE0 = 0; g_cntE1 = 0;
        g_s1[0] = 0; g_s2[0] = 0;
        g_flag1[0] = 1; g_flag2[0] = 1;
        g_deg[0] = 0;
        g_hlin_done = 0;
        atomicOr(&g_bm1[0], 1u);
        atomicOr(&g_bm2[0], 1u);
    }
}

// ---------------------------------------------------------------------------
__device__ __forceinline__ void s1_one(const int* __restrict__ src, int d, int idx) {
    if (d == 0) {
        int s = __ldcg(&src[idx]);
        int p = atomicAdd(&g_cntE0, 1);
        if (p < E0CAP) g_e0[p] = s;
        if (atomicCAS(&g_flag1[s], 0, -1) == 0) {
            int q = atomicAdd(&g_cnt1, 1);
            if (q < S1CAP) g_s1[q] = s;
            g_flag1[s] = q + 1;
            atomicOr(&g_bm1[s >> 5], 1u << (s & 31));
            if (atomicCAS(&g_flag2[s], 0, -1) == 0) {
                int r = atomicAdd(&g_cnt2, 1);
                if (r < ECAP) g_s2[r] = s;
                g_flag2[s] = r + 1;
                atomicOr(&g_bm2[s >> 5], 1u << (s & 31));
            }
        }
    }
}

__global__ void __launch_bounds__(SCAN_T)
k_scan1(const int* __restrict__ src, const int* __restrict__ dst, int E) {
    cudaGridDependencySynchronize();
    int gid = blockIdx.x * SCAN_T + threadIdx.x;
    int nth = SCAN_B * SCAN_T;
    int E4 = E >> 2;
    const int4* d4 = (const int4*)dst;
    int i = gid;
    for (; i + 3 * nth < E4; i += 4 * nth) {
        int4 v0 = __ldcg(&d4[i]);
        int4 v1 = __ldcg(&d4[i + nth]);
        int4 v2 = __ldcg(&d4[i + 2 * nth]);
        int4 v3 = __ldcg(&d4[i + 3 * nth]);
        int j;
        j = i;           s1_one(src, v0.x, 4*j); s1_one(src, v0.y, 4*j+1); s1_one(src, v0.z, 4*j+2); s1_one(src, v0.w, 4*j+3);
        j = i + nth;     s1_one(src, v1.x, 4*j); s1_one(src, v1.y, 4*j+1); s1_one(src, v1.z, 4*j+2); s1_one(src, v1.w, 4*j+3);
        j = i + 2 * nth; s1_one(src, v2.x, 4*j); s1_one(src, v2.y, 4*j+1); s1_one(src, v2.z, 4*j+2); s1_one(src, v2.w, 4*j+3);
        j = i + 3 * nth; s1_one(src, v3.x, 4*j); s1_one(src, v3.y, 4*j+1); s1_one(src, v3.z, 4*j+2); s1_one(src, v3.w, 4*j+3);
    }
    for (; i < E4; i += nth) {
        int4 v = __ldcg(&d4[i]);
        s1_one(src, v.x, 4*i); s1_one(src, v.y, 4*i+1); s1_one(src, v.z, 4*i+2); s1_one(src, v.w, 4*i+3);
    }
    for (int j = (E4 << 2) + gid; j < E; j += nth) s1_one(src, __ldcg(&dst[j]), j);
}

// ---------------------------------------------------------------------------
__device__ __forceinline__ void s2_one(const unsigned* sbm,
                                       const int* __restrict__ src, int d, int idx) {
    if ((sbm[d >> 5] >> (d & 31)) & 1u) {
        int s = __ldcg(&src[idx]);
        int p = atomicAdd(&g_cntE1, 1);
        if (p < ECAP) g_e1[p] = make_int2(s, d);
        if (atomicCAS(&g_flag2[s], 0, -1) == 0) {
            int r = atomicAdd(&g_cnt2, 1);
            if (r < ECAP) g_s2[r] = s;
            g_flag2[s] = r + 1;
            atomicOr(&g_bm2[s >> 5], 1u << (s & 31));
        }
    }
}

__global__ void __launch_bounds__(SCAN_T)
k_scan2(const int* __restrict__ src, const int* __restrict__ dst, int E) {
    __shared__ unsigned sbm[BMW];
    cudaGridDependencySynchronize();
    for (int k = threadIdx.x; k < BMW; k += SCAN_T) sbm[k] = __ldg(&g_bm1[k]);
    __syncthreads();
    int gid = blockIdx.x * SCAN_T + threadIdx.x;
    int nth = SCAN_B * SCAN_T;
    int E4 = E >> 2;
    const int4* d4 = (const int4*)dst;
    int i = gid;
    for (; i + 3 * nth < E4; i += 4 * nth) {
        int4 v0 = __ldcg(&d4[i]);
        int4 v1 = __ldcg(&d4[i + nth]);
        int4 v2 = __ldcg(&d4[i + 2 * nth]);
        int4 v3 = __ldcg(&d4[i + 3 * nth]);
        int j;
        j = i;           s2_one(sbm, src, v0.x, 4*j); s2_one(sbm, src, v0.y, 4*j+1); s2_one(sbm, src, v0.z, 4*j+2); s2_one(sbm, src, v0.w, 4*j+3);
        j = i + nth;     s2_one(sbm, src, v1.x, 4*j); s2_one(sbm, src, v1.y, 4*j+1); s2_one(sbm, src, v1.z, 4*j+2); s2_one(sbm, src, v1.w, 4*j+3);
        j = i + 2 * nth; s2_one(sbm, src, v2.x, 4*j); s2_one(sbm, src, v2.y, 4*j+1); s2_one(sbm, src, v2.z, 4*j+2); s2_one(sbm, src, v2.w, 4*j+3);
        j = i + 3 * nth; s2_one(sbm, src, v3.x, 4*j); s2_one(sbm, src, v3.y, 4*j+1); s2_one(sbm, src, v3.z, 4*j+2); s2_one(sbm, src, v3.w, 4*j+3);
    }
    for (; i < E4; i += nth) {
        int4 v = __ldcg(&d4[i]);
        s2_one(sbm, src, v.x, 4*i); s2_one(sbm, src, v.y, 4*i+1); s2_one(sbm, src, v.z, 4*i+2); s2_one(sbm, src, v.w, 4*i+3);
    }
    for (int j = (E4 << 2) + gid; j < E; j += nth) {
        int d = __ldcg(&dst[j]);
        s2_one(sbm, src, d, j);
    }
}

// ---------------------------------------------------------------------------
// hlin = x[:,u] @ W1 for u in S2. Depends ONLY on scan2. Triggers PDL right
// after gridsync so the next kernel (scan3, also scan2-dependent only) gets
// launched and runs concurrently. Completion signalled via g_hlin_done.
__global__ void __launch_bounds__(SCAN_T)
k_hlin(const float* __restrict__ x, const float* __restrict__ W1, int N) {
    __shared__ float sW1[IND * H];   // 32 KB
    __shared__ float sx[4][IND];     // 2 KB
    cudaGridDependencySynchronize();
    cudaTriggerProgrammaticLaunchCompletion();   // let scan3 launch now
    for (int k = threadIdx.x; k < IND * H; k += SCAN_T) sW1[k] = W1[k];
    __syncthreads();
    int m2 = g_cnt2; if (m2 > ECAP) m2 = ECAP;
    int g  = threadIdx.x >> 7;
    int lt = threadIdx.x & 127;
    for (int base = blockIdx.x * 4; base < m2; base += HLIN_B * 4) {
        int j = base + g;
        int u = (j < m2) ? g_s2[j] : -1;
        if (u >= 0) sx[g][lt] = __ldg(&x[(size_t)lt * N + u]);
        __syncthreads();
        if (u >= 0 && lt < H) {
            float acc = 0.0f;
            #pragma unroll
            for (int d = 0; d < IND; d++) acc += sx[g][d] * sW1[d * H + lt];
            g_hlin[j][lt] = acc;
        }
        __syncthreads();
    }
    __syncthreads();
    if (threadIdx.x == 0) {
        __threadfence();
        atomicAdd(&g_hlin_done, 1u);
    }
}

// ---------------------------------------------------------------------------
// Degree scan (bm2-gated). Runs concurrently with k_hlin.
__global__ void __launch_bounds__(SCAN_T)
k_scan3(const int* __restrict__ dst, int E) {
    __shared__ unsigned sbm[BMW];
    cudaGridDependencySynchronize();
    for (int k = threadIdx.x; k < BMW; k += SCAN_T) sbm[k] = __ldg(&g_bm2[k]);
    __syncthreads();
    int gid = blockIdx.x * SCAN_T + threadIdx.x;
    int nth = SCAN_B * SCAN_T;
    int E4 = E >> 2;
    const int4* d4 = (const int4*)dst;
    #define S3(dd) if ((sbm[(dd) >> 5] >> ((dd) & 31)) & 1u) atomicAdd(&g_deg[dd], 1)
    int i = gid;
    for (; i + 3 * nth < E4; i += 4 * nth) {
        int4 v0 = __ldcg(&d4[i]);
        int4 v1 = __ldcg(&d4[i + nth]);
        int4 v2 = __ldcg(&d4[i + 2 * nth]);
        int4 v3 = __ldcg(&d4[i + 3 * nth]);
        S3(v0.x); S3(v0.y); S3(v0.z); S3(v0.w);
        S3(v1.x); S3(v1.y); S3(v1.z); S3(v1.w);
        S3(v2.x); S3(v2.y); S3(v2.z); S3(v2.w);
        S3(v3.x); S3(v3.y); S3(v3.z); S3(v3.w);
    }
    for (; i < E4; i += nth) {
        int4 v = __ldcg(&d4[i]);
        S3(v.x); S3(v.y); S3(v.z); S3(v.w);
    }
    for (int j = (E4 << 2) + gid; j < E; j += nth) { int dd = __ldcg(&dst[j]); S3(dd); }
    #undef S3
}

// ---------------------------------------------------------------------------
// Layer-1 aggregation. PDL orders it after scan3; hlin completion is checked
// explicitly via g_hlin_done (hlin may still be in flight when scan3 exits).
__global__ void k_agg(void) {
    cudaGridDependencySynchronize();
    if (threadIdx.x == 0) {
        while (atomicAdd(&g_hlin_done, 0u) < (unsigned)HLIN_B) { }
        __threadfence();
    }
    __syncthreads();
    int sub = threadIdx.x >> 6;          // 4 groups of 64 per block
    int tt  = threadIdx.x & 63;
    int ng  = gridDim.x * 4;
    int gi  = blockIdx.x * 4 + sub;
    int m1 = g_cnt1; if (m1 > S1CAP) m1 = S1CAP;
    for (int j = gi; j < m1; j += ng) {
        int u  = g_s1[j];
        float di = rsqrtf((float)g_deg[u] + 1.0f);
        int p2 = g_flag2[u] - 1;
        atomicAdd(&g_acc1[j][tt], di * di * __ldcg(&g_hlin[p2][tt]));
    }
    int mE = g_cntE1; if (mE > ECAP) mE = ECAP;
    for (int e = gi; e < mE; e += ng) {
        int2 ed = g_e1[e];
        int dp = g_flag1[ed.y] - 1;
        int sp = g_flag2[ed.x] - 1;
        float nrm = rsqrtf((float)g_deg[ed.x] + 1.0f) * rsqrtf((float)g_deg[ed.y] + 1.0f);
        atomicAdd(&g_acc1[dp][tt], nrm * __ldcg(&g_hlin[sp][tt]));
    }
}

// ---------------------------------------------------------------------------
// Single block: h2 for all S1 nodes, node-0 layer-2 aggregation, LSTM, FC.
__global__ void __launch_bounds__(512)
k_tail(const float* __restrict__ b1, const float* __restrict__ W2,
       const float* __restrict__ b2, const float* __restrict__ w_ih,
       const float* __restrict__ b_ih, const float* __restrict__ b_hh,
       const float* __restrict__ fc_w, const float* __restrict__ fc_b,
       float* __restrict__ out) {
    __shared__ float sW2[H * H];        // 16 KB
    __shared__ float h1buf[8][H];       // 2 KB
    __shared__ float z[H], gates[4 * H], red[H];
    __shared__ float scof[256];
    __shared__ int   sspb[256];

    cudaGridDependencySynchronize();
    int tid = threadIdx.x;
    for (int k = tid; k < H * H; k += 512) sW2[k] = W2[k];
    __syncthreads();

    int m1 = g_cnt1; if (m1 > S1CAP) m1 = S1CAP;
    int sub = tid >> 6, tt = tid & 63;
    for (int j0 = 0; j0 < m1; j0 += 8) {
        int j = j0 + sub;
        if (j < m1) h1buf[sub][tt] = fmaxf(g_acc1[j][tt] + b1[tt], 0.0f);
        __syncthreads();
        if (j < m1) {
            float acc = 0.0f;
            #pragma unroll
            for (int h = 0; h < H; h++) acc += h1buf[sub][h] * sW2[h * H + tt];
            g_h2[j][tt] = acc;
        }
        __syncthreads();
    }

    // node-0 layer-2 aggregation
    int m0 = g_cntE0; if (m0 > E0CAP) m0 = E0CAP;
    float d0 = rsqrtf((float)g_deg[0] + 1.0f);
    float zv = 0.0f;
    if (tid < H) zv = b2[tid] + d0 * d0 * g_h2[0][tid];
    for (int base = 0; base < m0; base += 256) {
        int k = base + tid;
        if (tid < 256 && k < m0) {
            int s = g_e0[k];
            scof[tid] = rsqrtf((float)g_deg[s] + 1.0f) * d0;
            sspb[tid] = g_flag1[s] - 1;
        }
        __syncthreads();
        int lim = m0 - base; if (lim > 256) lim = 256;
        if (tid < H)
            for (int e = 0; e < lim; e++) zv += scof[e] * g_h2[sspb[e]][tid];
        __syncthreads();
    }
    if (tid < H) z[tid] = zv;
    __syncthreads();

    if (tid < 4 * H) {
        float a = b_ih[tid] + b_hh[tid];
        #pragma unroll
        for (int h = 0; h < H; h++) a += __ldg(&w_ih[tid * H + h]) * z[h];
        gates[tid] = a;
    }
    __syncthreads();
    if (tid < H) {
        float ig = gates[tid];
        float gg = gates[2 * H + tid];
        float og = gates[3 * H + tid];
        float si = 1.0f / (1.0f + expf(-ig));
        float c  = si * tanhf(gg);
        float so = 1.0f / (1.0f + expf(-og));
        float hy = so * tanhf(c);
        red[tid] = hy * fc_w[tid];
    }
    __syncthreads();
    if (tid == 0) {
        float s = 0.0f;
        for (int k = 0; k < H; k++) s += red[k];
        out[0] = s + fc_b[0];
    }
}

// ---------------------------------------------------------------------------
static void launch_pdl(const void* func, dim3 grid, dim3 block, void** args) {
    cudaLaunchConfig_t cfg = {};
    cfg.gridDim = grid;
    cfg.blockDim = block;
    cfg.dynamicSmemBytes = 0;
    cfg.stream = 0;                      // legacy default stream (captured)
    cudaLaunchAttribute attr[1];
    attr[0].id = cudaLaunchAttributeProgrammaticStreamSerialization;
    attr[0].val.programmaticStreamSerializationAllowed = 1;
    cfg.attrs = attr;
    cfg.numAttrs = 1;
    cudaLaunchKernelExC(&cfg, func, args);
}

extern "C" void kernel_launch(void* const* d_in, const int* in_sizes, int n_in,
                              void* d_out, int out_size) {
    const float* x    = (const float*)d_in[0];
    const int*   ei   = (const int*)d_in[1];
    const float* W1   = (const float*)d_in[2];
    const float* b1   = (const float*)d_in[3];
    const float* W2   = (const float*)d_in[4];
    const float* b2   = (const float*)d_in[5];
    const float* w_ih = (const float*)d_in[6];
    // d_in[7] = w_hh (unused: h0 = c0 = 0)
    const float* b_ih = (const float*)d_in[8];
    const float* b_hh = (const float*)d_in[9];
    const float* fc_w = (const float*)d_in[10];
    const float* fc_b = (const float*)d_in[11];
    float* out = (float*)d_out;

    int N = in_sizes[0] / IND;
    int E = in_sizes[1] / 2;
    const int* src = ei;
    const int* dst = ei + E;

    {
        void* a[] = {};
        launch_pdl((const void*)k_init, dim3(1), dim3(512), a);
    }
    {
        void* a[] = {(void*)&src, (void*)&dst, (void*)&E};
        launch_pdl((const void*)k_scan1, dim3(SCAN_B), dim3(SCAN_T), a);
        launch_pdl((const void*)k_scan2, dim3(SCAN_B), dim3(SCAN_T), a);
    }
    {
        void* a[] = {(void*)&x, (void*)&W1, (void*)&N};
        launch_pdl((const void*)k_hlin, dim3(HLIN_B), dim3(SCAN_T), a);
    }
    {
        void* a[] = {(void*)&dst, (void*)&E};
        launch_pdl((const void*)k_scan3, dim3(SCAN_B), dim3(SCAN_T), a);
    }
    {
        void* a[] = {};
        launch_pdl((const void*)k_agg, dim3(148), dim3(256), a);
    }
    {
        void* a[] = {(void*)&b1, (void*)&W2, (void*)&b2, (void*)&w_ih,
                     (void*)&b_ih, (void*)&b_hh, (void*)&fc_w, (void*)&fc_b,
                     (void*)&out};
        launch_pdl((const void*)k_tail, dim3(1), dim3(512), a);
    }
}

// round 9
// speedup vs baseline: 1.0537x; 1.0537x over previous
#include <cuda_runtime.h>
#include <math.h>

// ---------------------------------------------------------------------------
// GCN(2)->node0->LSTM->FC. Only the 2-hop in-neighborhood of node 0 matters:
// S1 = in-neighbors of 0 (~32), S2 = in-neighbors of S1 (~1100).
// Six kernels (plain launches; launch edges = barriers + L1 flush):
//   1 init  : incremental reset of prev-run entries (1 block), seed node 0
//   2 scan1 : dst==0            -> e0 list, S1 set, bm1
//   3 scan2 : dst in bm1 (SMEM) -> e1 list, S2 set, bm2
//   4 s3h   : HETEROGENEOUS blocks, both halves depend only on scan2:
//               blocks 0..147   : hlin = x[:,u]@W1 for u in S2 (16-node stage,
//                                 high-MLP gather, single sync)
//               blocks 148..443 : dst in bm2 (SMEM) -> deg
//   5 agg   : layer-1 aggregation into acc1 (self loops + e1, atomics)
//   6 tail  : one block: h2 = relu(acc1+b1)@W2 ; node-0 agg ; LSTM ; FC
// ---------------------------------------------------------------------------

#define NN_MAX   100000
#define IND      128
#define H        64
#define S1CAP    512
#define E0CAP    2048
#define ECAP     32768
#define BMW      ((NN_MAX + 31) / 32)   // 3125 words = 12.5 KB
#define SCAN_B   296
#define SCAN_T   512
#define HLIN_B   148
#define HN       16                      // nodes staged per hlin block

static __device__ int      g_deg[NN_MAX];
static __device__ int      g_flag1[NN_MAX];   // pos+1 in S1 (0 = not member)
static __device__ int      g_flag2[NN_MAX];   // pos+1 in S2
static __device__ unsigned g_bm1[BMW];
static __device__ unsigned g_bm2[BMW];
static __device__ int      g_s1[S1CAP];
static __device__ int      g_e0[E0CAP];       // src of edges with dst==0
static __device__ int      g_s2[ECAP];
static __device__ int2     g_e1[ECAP];        // edges with dst in S1
static __device__ int      g_cnt1, g_cnt2, g_cntE0, g_cntE1;
static __device__ float    g_hlin[ECAP][H];
static __device__ float    g_acc1[S1CAP][H];
static __device__ float    g_h2[S1CAP][H];

// ---------------------------------------------------------------------------
// Incremental init: reset exactly the entries the previous run touched,
// then seed node 0. First call sees counters==0 (static zero-init) -> no-op
// loops, seed only. Always leaves the identical canonical state.
__global__ void k_init(void) {
    int tid = threadIdx.x;
    int m1 = g_cnt1; if (m1 > S1CAP) m1 = S1CAP;
    int m2 = g_cnt2; if (m2 > ECAP)  m2 = ECAP;
    for (int j = 1 + tid; j < m1; j += 512) {
        int u = g_s1[j];
        g_flag1[u] = 0;
        atomicAnd(&g_bm1[u >> 5], ~(1u << (u & 31)));
    }
    for (int j = 1 + tid; j < m2; j += 512) {
        int u = g_s2[j];
        g_flag2[u] = 0;
        g_deg[u]   = 0;
        atomicAnd(&g_bm2[u >> 5], ~(1u << (u & 31)));
    }
    for (int k = tid; k < m1 * H; k += 512) ((float*)g_acc1)[k] = 0.0f;
    __syncthreads();
    if (tid == 0) {
        g_cnt1 = 1; g_cnt2 = 1; g_cntE0 = 0; g_cntE1 = 0;
        g_s1[0] = 0; g_s2[0] = 0;
        g_flag1[0] = 1; g_flag2[0] = 1;
        g_deg[0] = 0;
        atomicOr(&g_bm1[0], 1u);
        atomicOr(&g_bm2[0], 1u);
    }
}

// ---------------------------------------------------------------------------
__device__ __forceinline__ void s1_one(const int* __restrict__ src, int d, int idx) {
    if (d == 0) {
        int s = __ldcg(&src[idx]);
        int p = atomicAdd(&g_cntE0, 1);
        if (p < E0CAP) g_e0[p] = s;
        if (atomicCAS(&g_flag1[s], 0, -1) == 0) {
            int q = atomicAdd(&g_cnt1, 1);
            if (q < S1CAP) g_s1[q] = s;
            g_flag1[s] = q + 1;
            atomicOr(&g_bm1[s >> 5], 1u << (s & 31));
            if (atomicCAS(&g_flag2[s], 0, -1) == 0) {
                int r = atomicAdd(&g_cnt2, 1);
                if (r < ECAP) g_s2[r] = s;
                g_flag2[s] = r + 1;
                atomicOr(&g_bm2[s >> 5], 1u << (s & 31));
            }
        }
    }
}

__global__ void __launch_bounds__(SCAN_T)
k_scan1(const int* __restrict__ src, const int* __restrict__ dst, int E) {
    int gid = blockIdx.x * SCAN_T + threadIdx.x;
    int nth = SCAN_B * SCAN_T;
    int E4 = E >> 2;
    const int4* d4 = (const int4*)dst;
    int i = gid;
    for (; i + 3 * nth < E4; i += 4 * nth) {
        int4 v0 = __ldcg(&d4[i]);
        int4 v1 = __ldcg(&d4[i + nth]);
        int4 v2 = __ldcg(&d4[i + 2 * nth]);
        int4 v3 = __ldcg(&d4[i + 3 * nth]);
        int j;
        j = i;           s1_one(src, v0.x, 4*j); s1_one(src, v0.y, 4*j+1); s1_one(src, v0.z, 4*j+2); s1_one(src, v0.w, 4*j+3);
        j = i + nth;     s1_one(src, v1.x, 4*j); s1_one(src, v1.y, 4*j+1); s1_one(src, v1.z, 4*j+2); s1_one(src, v1.w, 4*j+3);
        j = i + 2 * nth; s1_one(src, v2.x, 4*j); s1_one(src, v2.y, 4*j+1); s1_one(src, v2.z, 4*j+2); s1_one(src, v2.w, 4*j+3);
        j = i + 3 * nth; s1_one(src, v3.x, 4*j); s1_one(src, v3.y, 4*j+1); s1_one(src, v3.z, 4*j+2); s1_one(src, v3.w, 4*j+3);
    }
    for (; i < E4; i += nth) {
        int4 v = __ldcg(&d4[i]);
        s1_one(src, v.x, 4*i); s1_one(src, v.y, 4*i+1); s1_one(src, v.z, 4*i+2); s1_one(src, v.w, 4*i+3);
    }
    for (int j = (E4 << 2) + gid; j < E; j += nth) s1_one(src, __ldcg(&dst[j]), j);
}

// ---------------------------------------------------------------------------
__device__ __forceinline__ void s2_one(const unsigned* sbm,
                                       const int* __restrict__ src, int d, int idx) {
    if ((sbm[d >> 5] >> (d & 31)) & 1u) {
        int s = __ldcg(&src[idx]);
        int p = atomicAdd(&g_cntE1, 1);
        if (p < ECAP) g_e1[p] = make_int2(s, d);
        if (atomicCAS(&g_flag2[s], 0, -1) == 0) {
            int r = atomicAdd(&g_cnt2, 1);
            if (r < ECAP) g_s2[r] = s;
            g_flag2[s] = r + 1;
            atomicOr(&g_bm2[s >> 5], 1u << (s & 31));
        }
    }
}

__global__ void __launch_bounds__(SCAN_T)
k_scan2(const int* __restrict__ src, const int* __restrict__ dst, int E) {
    __shared__ unsigned sbm[BMW];
    for (int k = threadIdx.x; k < BMW; k += SCAN_T) sbm[k] = __ldg(&g_bm1[k]);
    __syncthreads();
    int gid = blockIdx.x * SCAN_T + threadIdx.x;
    int nth = SCAN_B * SCAN_T;
    int E4 = E >> 2;
    const int4* d4 = (const int4*)dst;
    int i = gid;
    for (; i + 3 * nth < E4; i += 4 * nth) {
        int4 v0 = __ldcg(&d4[i]);
        int4 v1 = __ldcg(&d4[i + nth]);
        int4 v2 = __ldcg(&d4[i + 2 * nth]);
        int4 v3 = __ldcg(&d4[i + 3 * nth]);
        int j;
        j = i;           s2_one(sbm, src, v0.x, 4*j); s2_one(sbm, src, v0.y, 4*j+1); s2_one(sbm, src, v0.z, 4*j+2); s2_one(sbm, src, v0.w, 4*j+3);
        j = i + nth;     s2_one(sbm, src, v1.x, 4*j); s2_one(sbm, src, v1.y, 4*j+1); s2_one(sbm, src, v1.z, 4*j+2); s2_one(sbm, src, v1.w, 4*j+3);
        j = i + 2 * nth; s2_one(sbm, src, v2.x, 4*j); s2_one(sbm, src, v2.y, 4*j+1); s2_one(sbm, src, v2.z, 4*j+2); s2_one(sbm, src, v2.w, 4*j+3);
        j = i + 3 * nth; s2_one(sbm, src, v3.x, 4*j); s2_one(sbm, src, v3.y, 4*j+1); s2_one(sbm, src, v3.z, 4*j+2); s2_one(sbm, src, v3.w, 4*j+3);
    }
    for (; i < E4; i += nth) {
        int4 v = __ldcg(&d4[i]);
        s2_one(sbm, src, v.x, 4*i); s2_one(sbm, src, v.y, 4*i+1); s2_one(sbm, src, v.z, 4*i+2); s2_one(sbm, src, v.w, 4*i+3);
    }
    for (int j = (E4 << 2) + gid; j < E; j += nth) {
        int d = __ldcg(&dst[j]);
        s2_one(sbm, src, d, j);
    }
}

// ---------------------------------------------------------------------------
// Heterogeneous kernel: blocks [0, HLIN_B) do hlin; blocks [HLIN_B, HLIN_B +
// SCAN_B) do the bm2-gated degree scan. Both depend only on scan2 -> fully
// concurrent, no ordering needed. Shared byte-buffer reinterpreted per branch.
__global__ void __launch_bounds__(SCAN_T, 3)
k_s3h(const int* __restrict__ dst, int E,
      const float* __restrict__ x, const float* __restrict__ W1, int N) {
    __shared__ __align__(16) unsigned char sbuf[40960];   // 40 KB
    int tid = threadIdx.x;

    if (blockIdx.x < HLIN_B) {
        // ---------------- hlin branch ----------------
        float* sW1 = (float*)sbuf;                          // 32 KB
        float (*sx)[IND] = (float(*)[IND])(sbuf + IND * H * 4); // 8 KB
        for (int k = tid; k < IND * H; k += SCAN_T) sW1[k] = W1[k];
        int m2 = g_cnt2; if (m2 > ECAP) m2 = ECAP;
        for (int base = blockIdx.x * HN; base < m2; base += HLIN_B * HN) {
            // stage: 16 nodes x 128 dims = 2048 scattered loads, 4/thread in flight
            for (int k = tid; k < HN * IND; k += SCAN_T) {
                int node = k >> 7;
                int d    = k & 127;
                int j    = base + node;
                if (j < m2) sx[node][d] = __ldg(&x[(size_t)d * N + g_s2[j]]);
            }
            __syncthreads();
            // dot: 16 nodes x 64 outputs = 1024 tasks, 2/thread
            for (int k = tid; k < HN * H; k += SCAN_T) {
                int node = k >> 6;
                int o    = k & 63;
                int j    = base + node;
                if (j < m2) {
                    float acc = 0.0f;
                    #pragma unroll
                    for (int d = 0; d < IND; d++) acc += sx[node][d] * sW1[d * H + o];
                    g_hlin[j][o] = acc;
                }
            }
            __syncthreads();
        }
    } else {
        // ---------------- degree-scan branch ----------------
        unsigned* sbm = (unsigned*)sbuf;                    // 12.5 KB
        for (int k = tid; k < BMW; k += SCAN_T) sbm[k] = __ldg(&g_bm2[k]);
        __syncthreads();
        int sbid = blockIdx.x - HLIN_B;
        int gid = sbid * SCAN_T + tid;
        int nth = SCAN_B * SCAN_T;
        int E4 = E >> 2;
        const int4* d4 = (const int4*)dst;
        #define S3(dd) if ((sbm[(dd) >> 5] >> ((dd) & 31)) & 1u) atomicAdd(&g_deg[dd], 1)
        int i = gid;
        for (; i + 3 * nth < E4; i += 4 * nth) {
            int4 v0 = __ldcg(&d4[i]);
            int4 v1 = __ldcg(&d4[i + nth]);
            int4 v2 = __ldcg(&d4[i + 2 * nth]);
            int4 v3 = __ldcg(&d4[i + 3 * nth]);
            S3(v0.x); S3(v0.y); S3(v0.z); S3(v0.w);
            S3(v1.x); S3(v1.y); S3(v1.z); S3(v1.w);
            S3(v2.x); S3(v2.y); S3(v2.z); S3(v2.w);
            S3(v3.x); S3(v3.y); S3(v3.z); S3(v3.w);
        }
        for (; i < E4; i += nth) {
            int4 v = __ldcg(&d4[i]);
            S3(v.x); S3(v.y); S3(v.z); S3(v.w);
        }
        for (int j = (E4 << 2) + gid; j < E; j += nth) { int dd = __ldcg(&dst[j]); S3(dd); }
        #undef S3
    }
}

// ---------------------------------------------------------------------------
// Layer-1 aggregation: self loops for S1 nodes + e1 edge scatter.
__global__ void k_agg(void) {
    int sub = threadIdx.x >> 6;          // 4 groups of 64 per block
    int tt  = threadIdx.x & 63;
    int ng  = gridDim.x * 4;
    int gi  = blockIdx.x * 4 + sub;
    int m1 = g_cnt1; if (m1 > S1CAP) m1 = S1CAP;
    for (int j = gi; j < m1; j += ng) {
        int u  = g_s1[j];
        float di = rsqrtf((float)g_deg[u] + 1.0f);
        int p2 = g_flag2[u] - 1;
        atomicAdd(&g_acc1[j][tt], di * di * g_hlin[p2][tt]);
    }
    int mE = g_cntE1; if (mE > ECAP) mE = ECAP;
    for (int e = gi; e < mE; e += ng) {
        int2 ed = g_e1[e];
        int dp = g_flag1[ed.y] - 1;
        int sp = g_flag2[ed.x] - 1;
        float nrm = rsqrtf((float)g_deg[ed.x] + 1.0f) * rsqrtf((float)g_deg[ed.y] + 1.0f);
        atomicAdd(&g_acc1[dp][tt], nrm * g_hlin[sp][tt]);
    }
}

// ---------------------------------------------------------------------------
// Single block: h2 for all S1 nodes, node-0 layer-2 aggregation, LSTM, FC.
__global__ void __launch_bounds__(512)
k_tail(const float* __restrict__ b1, const float* __restrict__ W2,
       const float* __restrict__ b2, const float* __restrict__ w_ih,
       const float* __restrict__ b_ih, const float* __restrict__ b_hh,
       const float* __restrict__ fc_w, const float* __restrict__ fc_b,
       float* __restrict__ out) {
    __shared__ float sW2[H * H];        // 16 KB
    __shared__ float h1buf[8][H];       // 2 KB
    __shared__ float z[H], gates[4 * H], red[H];
    __shared__ float scof[256];
    __shared__ int   sspb[256];

    int tid = threadIdx.x;
    for (int k = tid; k < H * H; k += 512) sW2[k] = W2[k];
    __syncthreads();

    int m1 = g_cnt1; if (m1 > S1CAP) m1 = S1CAP;
    int sub = tid >> 6, tt = tid & 63;
    for (int j0 = 0; j0 < m1; j0 += 8) {
        int j = j0 + sub;
        if (j < m1) h1buf[sub][tt] = fmaxf(g_acc1[j][tt] + b1[tt], 0.0f);
        __syncthreads();
        if (j < m1) {
            float acc = 0.0f;
            #pragma unroll
            for (int h = 0; h < H; h++) acc += h1buf[sub][h] * sW2[h * H + tt];
            g_h2[j][tt] = acc;
        }
        __syncthreads();
    }

    // node-0 layer-2 aggregation
    int m0 = g_cntE0; if (m0 > E0CAP) m0 = E0CAP;
    float d0 = rsqrtf((float)g_deg[0] + 1.0f);
    float zv = 0.0f;
    if (tid < H) zv = b2[tid] + d0 * d0 * g_h2[0][tid];
    for (int base = 0; base < m0; base += 256) {
        int k = base + tid;
        if (tid < 256 && k < m0) {
            int s = g_e0[k];
            scof[tid] = rsqrtf((float)g_deg[s] + 1.0f) * d0;
            sspb[tid] = g_flag1[s] - 1;
        }
        __syncthreads();
        int lim = m0 - base; if (lim > 256) lim = 256;
        if (tid < H)
            for (int e = 0; e < lim; e++) zv += scof[e] * g_h2[sspb[e]][tid];
        __syncthreads();
    }
    if (tid < H) z[tid] = zv;
    __syncthreads();

    if (tid < 4 * H) {
        float a = b_ih[tid] + b_hh[tid];
        #pragma unroll
        for (int h = 0; h < H; h++) a += __ldg(&w_ih[tid * H + h]) * z[h];
        gates[tid] = a;
    }
    __syncthreads();
    if (tid < H) {
        float ig = gates[tid];
        float gg = gates[2 * H + tid];
        float og = gates[3 * H + tid];
        float si = 1.0f / (1.0f + expf(-ig));
        float c  = si * tanhf(gg);
        float so = 1.0f / (1.0f + expf(-og));
        float hy = so * tanhf(c);
        red[tid] = hy * fc_w[tid];
    }
    __syncthreads();
    if (tid == 0) {
        float s = 0.0f;
        for (int k = 0; k < H; k++) s += red[k];
        out[0] = s + fc_b[0];
    }
}

// ---------------------------------------------------------------------------
extern "C" void kernel_launch(void* const* d_in, const int* in_sizes, int n_in,
                              void* d_out, int out_size) {
    const float* x    = (const float*)d_in[0];
    const int*   ei   = (const int*)d_in[1];
    const float* W1   = (const float*)d_in[2];
    const float* b1   = (const float*)d_in[3];
    const float* W2   = (const float*)d_in[4];
    const float* b2   = (const float*)d_in[5];
    const float* w_ih = (const float*)d_in[6];
    // d_in[7] = w_hh (unused: h0 = c0 = 0)
    const float* b_ih = (const float*)d_in[8];
    const float* b_hh = (const float*)d_in[9];
    const float* fc_w = (const float*)d_in[10];
    const float* fc_b = (const float*)d_in[11];
    float* out = (float*)d_out;

    int N = in_sizes[0] / IND;
    int E = in_sizes[1] / 2;
    const int* src = ei;
    const int* dst = ei + E;

    k_init<<<1, 512>>>();
    k_scan1<<<SCAN_B, SCAN_T>>>(src, dst, E);
    k_scan2<<<SCAN_B, SCAN_T>>>(src, dst, E);
    k_s3h<<<HLIN_B + SCAN_B, SCAN_T>>>(dst, E, x, W1, N);
    k_agg<<<148, 256>>>();
    k_tail<<<1, 512>>>(b1, W2, b2, w_ih, b_ih, b_hh, fc_w, fc_b, out);
}